// round 1
// baseline (speedup 1.0000x reference)
#include <cuda_runtime.h>

// Problem constants (fixed by the reference)
#define BATCH 32
#define NDIM  2048
#define OUTD  100
#define NTHREADS 512
#define NWARPS   16          // 512 / 32
#define J_PER_WARP (NDIM / NWARPS)   // 128

// out[b,o] = sum_j rem[b,j] * W[j,o]
// rem[b,j] = (q[b,j] - float(NDIM*c[b,j] + S_b))^2,  c = (int)q (trunc), S_b = sum_j c[b,j]
// The reference's float reduce of the [N,N] broadcast is exact integer arithmetic
// (all partial sums < 2^24), so the int32 closed form is bit-identical.

__global__ __launch_bounds__(NTHREADS, 1)
void fused_rowstat_gemv_kernel(const float* __restrict__ q,
                               const float* __restrict__ W,
                               float* __restrict__ out)
{
    __shared__ float rem[NDIM];                       // 8 KB
    __shared__ int   warp_sums[NWARPS];
    __shared__ int   S_sh;
    __shared__ __align__(16) float partial[NWARPS][25][4];   // 6.25 KB

    const int b    = blockIdx.x;
    const int tid  = threadIdx.x;
    const int wid  = tid >> 5;
    const int lane = tid & 31;

    // ---- Phase 1: load q row (float4 per thread), int-cast, block sum ----
    const float4* q4 = reinterpret_cast<const float4*>(q + b * NDIM);
    float4 qv = q4[tid];                              // 512 * 4 = 2048 elems

    int cx = (int)qv.x, cy = (int)qv.y, cz = (int)qv.z, cw = (int)qv.w;
    int s = cx + cy + cz + cw;
    #pragma unroll
    for (int o = 16; o > 0; o >>= 1) s += __shfl_xor_sync(0xFFFFFFFFu, s, o);
    if (lane == 0) warp_sums[wid] = s;
    __syncthreads();
    if (tid < 32) {
        int v = (tid < NWARPS) ? warp_sums[tid] : 0;
        #pragma unroll
        for (int o = 16; o > 0; o >>= 1) v += __shfl_xor_sync(0xFFFFFFFFu, v, o);
        if (tid == 0) S_sh = v;
    }
    __syncthreads();
    const int S = S_sh;

    // ---- Phase 2: rem into shared ----
    float d0 = qv.x - (float)(NDIM * cx + S);
    float d1 = qv.y - (float)(NDIM * cy + S);
    float d2 = qv.z - (float)(NDIM * cz + S);
    float d3 = qv.w - (float)(NDIM * cw + S);
    float4 rv = make_float4(d0 * d0, d1 * d1, d2 * d2, d3 * d3);
    reinterpret_cast<float4*>(rem)[tid] = rv;
    __syncthreads();

    // ---- Phase 3: GEMV. warp = j-slice, lane = group of 4 contiguous outputs ----
    const int g = lane;                 // output group: o = 4g .. 4g+3 (g < 25)
    const int j0 = wid * J_PER_WARP;
    float ax = 0.f, ay = 0.f, az = 0.f, aw = 0.f;

    if (g < 25) {
        const float* Wg = W + g * 4;    // row j at Wg + j*OUTD, 16B aligned
        #pragma unroll 4
        for (int j = j0; j < j0 + J_PER_WARP; ++j) {
            float r = rem[j];           // smem broadcast
            float4 w = *reinterpret_cast<const float4*>(Wg + j * OUTD);
            ax = fmaf(r, w.x, ax);
            ay = fmaf(r, w.y, ay);
            az = fmaf(r, w.z, az);
            aw = fmaf(r, w.w, aw);
        }
        float4 av = make_float4(ax, ay, az, aw);
        *reinterpret_cast<float4*>(&partial[wid][g][0]) = av;
    }
    __syncthreads();

    // ---- Phase 4: deterministic cross-slice reduction, write out ----
    if (tid < OUTD) {
        const int gg = tid >> 2, oo = tid & 3;
        float sum = 0.f;
        #pragma unroll
        for (int w = 0; w < NWARPS; ++w) sum += partial[w][gg][oo];
        out[b * OUTD + tid] = sum;
    }
}

extern "C" void kernel_launch(void* const* d_in, const int* in_sizes, int n_in,
                              void* d_out, int out_size)
{
    const float* q = (const float*)d_in[0];   // [32, 2048] f32
    const float* W = (const float*)d_in[1];   // [2048, 100] f32
    float* out = (float*)d_out;               // [32, 100] f32
    (void)in_sizes; (void)n_in; (void)out_size;

    fused_rowstat_gemv_kernel<<<BATCH, NTHREADS>>>(q, W, out);
}

// round 2
// speedup vs baseline: 1.1802x; 1.1802x over previous
#include <cuda_runtime.h>

// Problem constants (fixed by the reference)
#define B      32
#define N      2048
#define OUTD   100
#define JSPLITS 16
#define JCHUNK (N / JSPLITS)        // 128
#define BPG    4                     // batches per group (W register reuse factor)
#define BGROUPS (B / BPG)            // 8
#define GRID   (JSPLITS * BGROUPS)   // 128 blocks -> one wave over 148 SMs
#define NT     512
#define NW     16                    // warps per block
#define J_PER_WARP (JCHUNK / NW)     // 8

// out[b,o] = sum_j rem[b,j] * W[j,o]
// rem[b,j] = (q[b,j] - float(N*c[b,j] + S_b))^2, c = (int)q, S_b = sum_j c[b,j]
// (exact vs the reference: all integer partials < 2^24, so the fp32 reduce of
//  the [N,N] broadcast equals the int32 closed form bit-for-bit)

__device__ float        g_partial[JSPLITS][B][OUTD];   // split-K partials
__device__ unsigned int g_count;                       // zero-initialized

__global__ __launch_bounds__(NT, 1)
void fused_rowstat_gemv_kernel(const float* __restrict__ q,
                               const float* __restrict__ W,
                               float* __restrict__ out)
{
    __shared__ float rem_sh[BPG][JCHUNK];        // 2 KB
    __shared__ float part_sh[NW][BPG * OUTD];    // 25.6 KB
    __shared__ int   qsum[NW];
    __shared__ int   S_sh[BPG];
    __shared__ bool  is_last;

    const int tid  = threadIdx.x;
    const int wid  = tid >> 5;
    const int lane = tid & 31;
    const int s    = blockIdx.x & (JSPLITS - 1);   // j-split index
    const int bg   = blockIdx.x >> 4;              // batch-group index
    const int j0   = s * JCHUNK;

    // ---- Phase 1: int row-sums S_b for the 4 rows (4 warps per row) ----
    {
        const int r       = wid >> 2;              // row within group: 0..3
        const int quarter = wid & 3;
        const int b       = bg * BPG + r;
        const float4* q4  = reinterpret_cast<const float4*>(q + b * N);
        const int t       = quarter * 32 + lane;   // 0..127
        int ss = 0;
        #pragma unroll
        for (int i = 0; i < 4; ++i) {              // 128 threads * 4 float4 = 2048
            float4 v = q4[t + 128 * i];
            ss += (int)v.x + (int)v.y + (int)v.z + (int)v.w;
        }
        #pragma unroll
        for (int o = 16; o > 0; o >>= 1) ss += __shfl_xor_sync(0xFFFFFFFFu, ss, o);
        if (lane == 0) qsum[wid] = ss;
    }
    __syncthreads();
    if (tid < BPG)
        S_sh[tid] = qsum[4*tid] + qsum[4*tid+1] + qsum[4*tid+2] + qsum[4*tid+3];
    __syncthreads();

    // ---- Phase 2: rem chunk for the 4 rows ----
    if (tid < JCHUNK) {
        float qv[BPG];
        #pragma unroll
        for (int r = 0; r < BPG; ++r)
            qv[r] = q[(bg * BPG + r) * N + j0 + tid];
        #pragma unroll
        for (int r = 0; r < BPG; ++r) {
            int   c = (int)qv[r];
            float d = qv[r] - (float)(N * c + S_sh[r]);
            rem_sh[r][tid] = d * d;
        }
    }
    __syncthreads();

    // ---- Phase 3: GEMV. warp = 8-j slice; lane g<25 owns outs 4g..4g+3.
    //      Each W float4 is reused for 4 batches (16 FFMA per LDG.128). ----
    const int g = lane;
    if (g < 25) {
        float acc[BPG][4];
        #pragma unroll
        for (int r = 0; r < BPG; ++r)
            acc[r][0] = acc[r][1] = acc[r][2] = acc[r][3] = 0.f;

        const int jw = wid * J_PER_WARP;
        const float* Wg = W + (size_t)(j0 + jw) * OUTD + g * 4;
        #pragma unroll
        for (int jj = 0; jj < J_PER_WARP; ++jj) {
            float4 w4 = *reinterpret_cast<const float4*>(Wg + jj * OUTD);
            #pragma unroll
            for (int r = 0; r < BPG; ++r) {
                float rv = rem_sh[r][jw + jj];     // smem broadcast
                acc[r][0] = fmaf(rv, w4.x, acc[r][0]);
                acc[r][1] = fmaf(rv, w4.y, acc[r][1]);
                acc[r][2] = fmaf(rv, w4.z, acc[r][2]);
                acc[r][3] = fmaf(rv, w4.w, acc[r][3]);
            }
        }
        #pragma unroll
        for (int r = 0; r < BPG; ++r)
            *reinterpret_cast<float4*>(&part_sh[wid][r * OUTD + g * 4]) =
                make_float4(acc[r][0], acc[r][1], acc[r][2], acc[r][3]);
    }
    __syncthreads();

    // ---- Phase 4: reduce 16 warps, emit split-K partial ----
    if (tid < BPG * OUTD) {                        // 400 outputs, 512 threads
        float ssum = 0.f;
        #pragma unroll
        for (int w = 0; w < NW; ++w) ssum += part_sh[w][tid];
        const int r = tid / OUTD;
        const int o = tid - r * OUTD;
        g_partial[s][bg * BPG + r][o] = ssum;
    }
    __threadfence();
    __syncthreads();

    // ---- Phase 5: last block reduces the 16 splits (deterministic order) ----
    if (tid == 0) {
        unsigned old = atomicAdd(&g_count, 1u);
        is_last = (old == GRID - 1);
        if (is_last) g_count = 0;                  // self-reset for next launch
    }
    __syncthreads();

    if (is_last) {
        for (int idx = tid; idx < B * OUTD; idx += NT) {
            const int b = idx / OUTD;
            const int o = idx - b * OUTD;
            float ssum = 0.f;
            #pragma unroll
            for (int sp = 0; sp < JSPLITS; ++sp)
                ssum += g_partial[sp][b][o];
            out[idx] = ssum;
        }
    }
}

extern "C" void kernel_launch(void* const* d_in, const int* in_sizes, int n_in,
                              void* d_out, int out_size)
{
    const float* q = (const float*)d_in[0];   // [32, 2048] f32
    const float* W = (const float*)d_in[1];   // [2048, 100] f32
    float* out = (float*)d_out;               // [32, 100] f32
    (void)in_sizes; (void)n_in; (void)out_size;

    fused_rowstat_gemv_kernel<<<GRID, NT>>>(q, W, out);
}

// round 3
// speedup vs baseline: 1.5263x; 1.2932x over previous
#include <cuda_runtime.h>

// Problem constants (fixed by the reference)
#define B       32
#define N       2048
#define OUTD    100
#define JSPLITS 16
#define JCHUNK  (N / JSPLITS)        // 128
#define BPG     4                    // batches per group (W register reuse)
#define BGROUPS (B / BPG)            // 8
#define GRID    (JSPLITS * BGROUPS)  // 128 blocks
#define NT      512
#define NW      16
#define J_PER_WARP (JCHUNK / NW)     // 8

// out[b,o] = sum_j rem[b,j] * W[j,o]
// rem[b,j] = (q[b,j] - float(N*c[b,j] + S_b))^2, c = (int)q, S_b = sum_j c[b,j]
// Exact vs reference: all integer partials < 2^24, so the reference's fp32
// reduce of the [N,N] broadcast equals the int32 closed form bit-for-bit.

__device__ float        g_partial[JSPLITS][B][OUTD];
__device__ unsigned int g_count[BGROUPS];            // zero-initialized

__global__ __launch_bounds__(NT, 1)
void fused_rowstat_gemv_kernel(const float* __restrict__ q,
                               const float* __restrict__ W,
                               float* __restrict__ out)
{
    __shared__ float4 rem4[BPG][JCHUNK / 4];     // 2 KB
    __shared__ float  part_sh[NW][BPG * OUTD];   // 25.6 KB
    __shared__ int    qsum[NW];
    __shared__ int    S_sh[BPG];
    __shared__ bool   is_last;

    const int tid  = threadIdx.x;
    const int wid  = tid >> 5;
    const int lane = tid & 31;
    const int s    = blockIdx.x & (JSPLITS - 1);   // j-split index
    const int bg   = blockIdx.x >> 4;              // batch-group index
    const int j0   = s * JCHUNK;

    // ---- Prefetch W into registers (block-index-dependent only). These
    //      8 independent LDG.128 retire behind the q-load/reduce phases. ----
    const int g  = lane;                 // output group: o = 4g..4g+3 (g<25)
    const int jw = wid * J_PER_WARP;
    float4 w4[J_PER_WARP];
    if (g < 25) {
        const float* Wg = W + (size_t)(j0 + jw) * OUTD + g * 4;
        #pragma unroll
        for (int jj = 0; jj < J_PER_WARP; ++jj)
            w4[jj] = *reinterpret_cast<const float4*>(Wg + jj * OUTD);
    }

    // ---- Phase 1: int row-sums for the 4 rows (4 warps per row), and keep
    //      the float4 that belongs to this block's j-chunk in a register. ----
    const int r       = wid >> 2;                  // row within group
    const int quarter = wid & 3;
    const int i_need  = s >> 2;                    // unroll step holding chunk s
    const bool owns_chunk = (quarter == (s & 3));
    float4 vkeep;
    {
        const float4* q4 = reinterpret_cast<const float4*>(q + (bg * BPG + r) * N);
        const int t = quarter * 32 + lane;         // 0..127
        int ss = 0;
        #pragma unroll
        for (int i = 0; i < 4; ++i) {
            float4 v = q4[t + 128 * i];
            ss += (int)v.x + (int)v.y + (int)v.z + (int)v.w;
            if (i == i_need) vkeep = v;
        }
        #pragma unroll
        for (int o = 16; o > 0; o >>= 1) ss += __shfl_xor_sync(0xFFFFFFFFu, ss, o);
        if (lane == 0) qsum[wid] = ss;
    }
    __syncthreads();
    if (tid < BPG)
        S_sh[tid] = qsum[4*tid] + qsum[4*tid+1] + qsum[4*tid+2] + qsum[4*tid+3];
    __syncthreads();

    // ---- Phase 2: rem chunk straight from registers (no q reload).
    //      Warp (4r + (s&3)) holds row r's chunk: float4 index lane of it. ----
    if (owns_chunk) {
        const int   S = S_sh[r];
        const float4 v = vkeep;
        int   c0 = (int)v.x, c1 = (int)v.y, c2 = (int)v.z, c3 = (int)v.w;
        float d0 = v.x - (float)(N * c0 + S);
        float d1 = v.y - (float)(N * c1 + S);
        float d2 = v.z - (float)(N * c2 + S);
        float d3 = v.w - (float)(N * c3 + S);
        rem4[r][lane] = make_float4(d0*d0, d1*d1, d2*d2, d3*d3);
    }
    __syncthreads();

    // ---- Phase 3: GEMV on registers + smem broadcast ----
    if (g < 25) {
        const float* rem = reinterpret_cast<const float*>(&rem4[0][0]);
        float acc[BPG][4];
        #pragma unroll
        for (int rr = 0; rr < BPG; ++rr)
            acc[rr][0] = acc[rr][1] = acc[rr][2] = acc[rr][3] = 0.f;
        #pragma unroll
        for (int jj = 0; jj < J_PER_WARP; ++jj) {
            #pragma unroll
            for (int rr = 0; rr < BPG; ++rr) {
                float rv = rem[rr * JCHUNK + jw + jj];
                acc[rr][0] = fmaf(rv, w4[jj].x, acc[rr][0]);
                acc[rr][1] = fmaf(rv, w4[jj].y, acc[rr][1]);
                acc[rr][2] = fmaf(rv, w4[jj].z, acc[rr][2]);
                acc[rr][3] = fmaf(rv, w4[jj].w, acc[rr][3]);
            }
        }
        #pragma unroll
        for (int rr = 0; rr < BPG; ++rr)
            *reinterpret_cast<float4*>(&part_sh[wid][rr * OUTD + g * 4]) =
                make_float4(acc[rr][0], acc[rr][1], acc[rr][2], acc[rr][3]);
    }
    __syncthreads();

    // ---- Phase 4: reduce 16 warps, emit split-K partial ----
    if (tid < BPG * OUTD) {                        // 400 of 512 threads
        float ssum = 0.f;
        #pragma unroll
        for (int w = 0; w < NW; ++w) ssum += part_sh[w][tid];
        const int rr = tid / OUTD;
        const int o  = tid - rr * OUTD;
        g_partial[s][bg * BPG + rr][o] = ssum;
    }
    __threadfence();
    __syncthreads();

    // ---- Phase 5: per-bgroup last block reduces its 16 splits ----
    if (tid == 0) {
        unsigned old = atomicAdd(&g_count[bg], 1u);
        is_last = (old == JSPLITS - 1);
        if (is_last) g_count[bg] = 0;              // self-reset for replay
    }
    __syncthreads();

    if (is_last && tid < BPG * OUTD) {
        const int rr = tid / OUTD;
        const int o  = tid - rr * OUTD;
        const int b  = bg * BPG + rr;
        float ssum = 0.f;
        #pragma unroll
        for (int sp = 0; sp < JSPLITS; ++sp)
            ssum += g_partial[sp][b][o];
        out[b * OUTD + o] = ssum;
    }
}

extern "C" void kernel_launch(void* const* d_in, const int* in_sizes, int n_in,
                              void* d_out, int out_size)
{
    const float* q = (const float*)d_in[0];   // [32, 2048] f32
    const float* W = (const float*)d_in[1];   // [2048, 100] f32
    float* out = (float*)d_out;               // [32, 100] f32
    (void)in_sizes; (void)n_in; (void)out_size;

    fused_rowstat_gemv_kernel<<<GRID, NT>>>(q, W, out);
}